// round 1
// baseline (speedup 1.0000x reference)
#include <cuda_runtime.h>
#include <cstdint>

// Problem constants (fixed by the dataset)
#define Bsz 2
#define Tseq 2048
#define Cdim 1024
#define Hn 16
#define HD 64
#define C3 (3 * Cdim)

// Scratch (allocation-free rule: __device__ globals)
__device__ float g_qkv[Bsz * Tseq * C3];    // [B,T,3C]  ~50.3 MB
__device__ float g_att[Bsz * Tseq * Cdim];  // [B,T,C]   ~16.8 MB

// ---------------------------------------------------------------------------
// SGEMM with bias: C[M,N] = A[M,K] @ B[K,N] + bias[N]
// BM=BN=128, BK=8, 256 threads, 8x8 per thread. Assumes M%128==0, N%128==0, K%8==0.
// ---------------------------------------------------------------------------
__global__ __launch_bounds__(256)
void sgemm_bias_kernel(const float* __restrict__ A, const float* __restrict__ B,
                       const float* __restrict__ bias, float* __restrict__ C,
                       int M, int N, int K) {
    __shared__ float As[8][128];
    __shared__ float Bs[8][128];

    const int tid = threadIdx.x;
    const int bm = blockIdx.y * 128;
    const int bn = blockIdx.x * 128;
    const int tx = tid % 16;        // output col group
    const int ty = tid / 16;        // output row group

    // A load: each thread loads float4 along K. arow in [0,128), acol in {0,4}
    const int arow = tid >> 1;
    const int acol = (tid & 1) * 4;
    // B load: each thread loads float4 along N. brow in [0,8), bcol in [0,128)
    const int brow = tid >> 5;
    const int bcol = (tid & 31) * 4;

    const float* Aptr = A + (size_t)(bm + arow) * K + acol;
    const float* Bptr = B + (size_t)brow * N + bn + bcol;

    float acc[8][8];
#pragma unroll
    for (int i = 0; i < 8; i++)
#pragma unroll
        for (int j = 0; j < 8; j++) acc[i][j] = 0.0f;

    for (int k0 = 0; k0 < K; k0 += 8) {
        float4 a4 = *reinterpret_cast<const float4*>(Aptr + k0);
        float4 b4 = *reinterpret_cast<const float4*>(Bptr + (size_t)k0 * N);

        As[acol + 0][arow] = a4.x;
        As[acol + 1][arow] = a4.y;
        As[acol + 2][arow] = a4.z;
        As[acol + 3][arow] = a4.w;
        *reinterpret_cast<float4*>(&Bs[brow][bcol]) = b4;
        __syncthreads();

#pragma unroll
        for (int kk = 0; kk < 8; kk++) {
            float ar[8], br[8];
#pragma unroll
            for (int i = 0; i < 8; i++) ar[i] = As[kk][ty * 8 + i];
#pragma unroll
            for (int j = 0; j < 8; j++) br[j] = Bs[kk][tx * 8 + j];
#pragma unroll
            for (int i = 0; i < 8; i++)
#pragma unroll
                for (int j = 0; j < 8; j++) acc[i][j] += ar[i] * br[j];
        }
        __syncthreads();
    }

#pragma unroll
    for (int i = 0; i < 8; i++) {
        const int row = bm + ty * 8 + i;
        float* crow = C + (size_t)row * N + bn + tx * 8;
#pragma unroll
        for (int j = 0; j < 8; j += 4) {
            const int col = bn + tx * 8 + j;
            float4 o;
            o.x = acc[i][j + 0] + bias[col + 0];
            o.y = acc[i][j + 1] + bias[col + 1];
            o.z = acc[i][j + 2] + bias[col + 2];
            o.w = acc[i][j + 3] + bias[col + 3];
            *reinterpret_cast<float4*>(crow + j) = o;
        }
    }
}

// ---------------------------------------------------------------------------
// Flash attention (causal). grid = (T/64, H, B), 256 threads.
// Q tile: 64 rows. KV tile: 32 rows. HD=64. Everything fp32.
// Reads q,k,v from g_qkv ([B,T,3C]); writes g_att ([B,T,C]).
// ---------------------------------------------------------------------------
#define BQ 64
#define BKV 32

__global__ __launch_bounds__(256)
void flash_attn_kernel(const float* __restrict__ qkv, float* __restrict__ out) {
    __shared__ float Qs[BQ][HD + 1];     // stride 65
    __shared__ float Ks[BKV][HD + 1];
    __shared__ float Vs[BKV][HD + 1];
    __shared__ float Ss[BQ][BKV + 1];    // stride 33
    __shared__ float m_s[BQ], l_s[BQ], alpha_s[BQ];

    const int qt = blockIdx.x;
    const int h  = blockIdx.y;
    const int b  = blockIdx.z;
    const int tid = threadIdx.x;
    const int tx = tid % 16;    // cols: qk -> 2 cols (tx*2), pv -> 4 cols (tx*4)
    const int ty = tid / 16;    // rows: 4 rows (ty*4)

    const float scale = 0.125f;  // 1/sqrt(64)

    const size_t base = ((size_t)b * Tseq) * C3 + (size_t)h * HD;

    // Load Q tile (64 x 64)
    for (int idx = tid; idx < BQ * HD; idx += 256) {
        const int r = idx / HD, d = idx % HD;
        Qs[r][d] = qkv[base + (size_t)(qt * BQ + r) * C3 + d];
    }
    if (tid < BQ) { m_s[tid] = -1e30f; l_s[tid] = 0.0f; }
    __syncthreads();

    float oacc[4][4];
#pragma unroll
    for (int i = 0; i < 4; i++)
#pragma unroll
        for (int j = 0; j < 4; j++) oacc[i][j] = 0.0f;

    const int n_kv = 2 * qt + 2;  // kv tiles covering [0, (qt+1)*64)

    for (int kt = 0; kt < n_kv; kt++) {
        // Load K,V tiles (32 x 64 each)
        for (int idx = tid; idx < BKV * HD; idx += 256) {
            const int r = idx / HD, d = idx % HD;
            const size_t rowoff = base + (size_t)(kt * BKV + r) * C3 + d;
            Ks[r][d] = qkv[rowoff + Cdim];
            Vs[r][d] = qkv[rowoff + 2 * Cdim];
        }
        __syncthreads();

        // S = scale * Q @ K^T with causal mask. 64x32 -> 8 per thread (4 rows x 2 cols)
        float sacc[4][2];
#pragma unroll
        for (int i = 0; i < 4; i++) { sacc[i][0] = 0.0f; sacc[i][1] = 0.0f; }
#pragma unroll 8
        for (int d = 0; d < HD; d++) {
            float q0 = Qs[ty * 4 + 0][d];
            float q1 = Qs[ty * 4 + 1][d];
            float q2 = Qs[ty * 4 + 2][d];
            float q3 = Qs[ty * 4 + 3][d];
            float k0 = Ks[tx * 2 + 0][d];
            float k1 = Ks[tx * 2 + 1][d];
            sacc[0][0] += q0 * k0; sacc[0][1] += q0 * k1;
            sacc[1][0] += q1 * k0; sacc[1][1] += q1 * k1;
            sacc[2][0] += q2 * k0; sacc[2][1] += q2 * k1;
            sacc[3][0] += q3 * k0; sacc[3][1] += q3 * k1;
        }
#pragma unroll
        for (int i = 0; i < 4; i++) {
            const int qg = qt * BQ + ty * 4 + i;
#pragma unroll
            for (int j = 0; j < 2; j++) {
                const int kg = kt * BKV + tx * 2 + j;
                float sv = sacc[i][j] * scale;
                if (kg > qg) sv = -1e30f;
                Ss[ty * 4 + i][tx * 2 + j] = sv;
            }
        }
        __syncthreads();

        // Row-wise streaming softmax (one thread per row)
        if (tid < BQ) {
            float mold = m_s[tid];
            float rmax = mold;
#pragma unroll 8
            for (int j = 0; j < BKV; j++) rmax = fmaxf(rmax, Ss[tid][j]);
            const float alpha = __expf(mold - rmax);
            float rsum = 0.0f;
#pragma unroll 8
            for (int j = 0; j < BKV; j++) {
                const float p = __expf(Ss[tid][j] - rmax);
                Ss[tid][j] = p;
                rsum += p;
            }
            l_s[tid] = l_s[tid] * alpha + rsum;
            m_s[tid] = rmax;
            alpha_s[tid] = alpha;
        }
        __syncthreads();

        // Rescale accumulator, O += P @ V. 64x64 -> 4x4 per thread.
        float al[4];
#pragma unroll
        for (int i = 0; i < 4; i++) al[i] = alpha_s[ty * 4 + i];
#pragma unroll
        for (int i = 0; i < 4; i++)
#pragma unroll
            for (int j = 0; j < 4; j++) oacc[i][j] *= al[i];

#pragma unroll 4
        for (int j = 0; j < BKV; j++) {
            float p0 = Ss[ty * 4 + 0][j];
            float p1 = Ss[ty * 4 + 1][j];
            float p2 = Ss[ty * 4 + 2][j];
            float p3 = Ss[ty * 4 + 3][j];
            float v0 = Vs[j][tx * 4 + 0];
            float v1 = Vs[j][tx * 4 + 1];
            float v2 = Vs[j][tx * 4 + 2];
            float v3 = Vs[j][tx * 4 + 3];
            oacc[0][0] += p0 * v0; oacc[0][1] += p0 * v1; oacc[0][2] += p0 * v2; oacc[0][3] += p0 * v3;
            oacc[1][0] += p1 * v0; oacc[1][1] += p1 * v1; oacc[1][2] += p1 * v2; oacc[1][3] += p1 * v3;
            oacc[2][0] += p2 * v0; oacc[2][1] += p2 * v1; oacc[2][2] += p2 * v2; oacc[2][3] += p2 * v3;
            oacc[3][0] += p3 * v0; oacc[3][1] += p3 * v1; oacc[3][2] += p3 * v2; oacc[3][3] += p3 * v3;
        }
        __syncthreads();
    }

    // Finalize: divide by l, write to g_att [B,T,C]
#pragma unroll
    for (int i = 0; i < 4; i++) {
        const int t = qt * BQ + ty * 4 + i;
        const float linv = 1.0f / l_s[ty * 4 + i];
        float* orow = out + ((size_t)b * Tseq + t) * Cdim + h * HD + tx * 4;
#pragma unroll
        for (int j = 0; j < 4; j++) orow[j] = oacc[i][j] * linv;
    }
}

// ---------------------------------------------------------------------------
// Launch
// ---------------------------------------------------------------------------
extern "C" void kernel_launch(void* const* d_in, const int* in_sizes, int n_in,
                              void* d_out, int out_size) {
    const float* x      = (const float*)d_in[0];  // [B,T,C]
    const float* w_attn = (const float*)d_in[1];  // [C,3C]
    const float* b_attn = (const float*)d_in[2];  // [3C]
    const float* w_proj = (const float*)d_in[3];  // [C,C]
    const float* b_proj = (const float*)d_in[4];  // [C]
    float* out = (float*)d_out;                   // [B,T,C]

    float* qkv = nullptr;
    float* att = nullptr;
    cudaGetSymbolAddress((void**)&qkv, g_qkv);
    cudaGetSymbolAddress((void**)&att, g_att);

    const int M = Bsz * Tseq;  // 4096

    // 1) qkv = x @ w_attn + b_attn     [4096,3072]
    {
        dim3 grid(C3 / 128, M / 128);
        sgemm_bias_kernel<<<grid, 256>>>(x, w_attn, b_attn, qkv, M, C3, Cdim);
    }

    // 2) attention -> g_att [B,T,C]
    {
        dim3 grid(Tseq / BQ, Hn, Bsz);
        flash_attn_kernel<<<grid, 256>>>(qkv, att);
    }

    // 3) out = att @ w_proj + b_proj   [4096,1024]
    {
        dim3 grid(Cdim / 128, M / 128);
        sgemm_bias_kernel<<<grid, 256>>>(att, w_proj, b_proj, out, M, Cdim, Cdim);
    }
}

// round 2
// speedup vs baseline: 2.8195x; 2.8195x over previous
#include <cuda_runtime.h>
#include <cstdint>

// Problem constants
#define Bsz 2
#define Tseq 2048
#define Cdim 1024
#define Hn 16
#define HD 64
#define C3 (3 * Cdim)

// Scratch (allocation-free rule: __device__ globals)
__device__ float g_qkv[Bsz * Tseq * C3];    // [B,T,3C]
__device__ float g_att[Bsz * Tseq * Cdim];  // [B,T,C]

// ---------------------------------------------------------------------------
// helpers
// ---------------------------------------------------------------------------
__device__ __forceinline__ uint32_t f2tf32(float x) {
    uint32_t r;
    asm("cvt.rna.tf32.f32 %0, %1;" : "=r"(r) : "f"(x));
    return r;
}

__device__ __forceinline__ void mma_tf32(float& c0, float& c1, float& c2, float& c3,
                                         uint32_t a0, uint32_t a1, uint32_t a2, uint32_t a3,
                                         uint32_t b0, uint32_t b1) {
    asm volatile(
        "mma.sync.aligned.m16n8k8.row.col.f32.tf32.tf32.f32 "
        "{%0,%1,%2,%3}, {%4,%5,%6,%7}, {%8,%9}, {%0,%1,%2,%3};"
        : "+f"(c0), "+f"(c1), "+f"(c2), "+f"(c3)
        : "r"(a0), "r"(a1), "r"(a2), "r"(a3), "r"(b0), "r"(b1));
}

__device__ __forceinline__ void cp_async16(void* dst, const void* src) {
    uint32_t d = (uint32_t)__cvta_generic_to_shared(dst);
    asm volatile("cp.async.ca.shared.global [%0], [%1], 16;" :: "r"(d), "l"(src));
}
__device__ __forceinline__ void cp_commit() { asm volatile("cp.async.commit_group;"); }
__device__ __forceinline__ void cp_wait0()  { asm volatile("cp.async.wait_group 0;"); }

// ---------------------------------------------------------------------------
// TF32 GEMM with bias: C[M,N] = A[M,K] @ B[K,N] + bias[N]
// BM=BN=128, BK=16, 256 threads (8 warps as 2x4), warp tile 64x32.
// ---------------------------------------------------------------------------
#define AS_STRIDE 20    // BK + 4  (bank: 20g+t all-distinct)
#define BS_STRIDE 136   // BN + 8  (bank: 8t+g all-distinct)

__global__ __launch_bounds__(256, 2)
void gemm_tf32_kernel(const float* __restrict__ A, const float* __restrict__ B,
                      const float* __restrict__ bias, float* __restrict__ C,
                      int M, int N, int K) {
    __shared__ float As[2][128 * AS_STRIDE];
    __shared__ float Bs[2][16 * BS_STRIDE];

    const int tid  = threadIdx.x;
    const int lane = tid & 31;
    const int wid  = tid >> 5;
    const int wm   = wid >> 2;      // 0..1
    const int wn   = wid & 3;       // 0..3
    const int g    = lane >> 2;     // group (row within frag)
    const int t    = lane & 3;      // thread in group
    const int bm   = blockIdx.y * 128;
    const int bn   = blockIdx.x * 128;

    float acc[4][4][4];
#pragma unroll
    for (int i = 0; i < 4; i++)
#pragma unroll
        for (int j = 0; j < 4; j++)
#pragma unroll
            for (int r = 0; r < 4; r++) acc[i][j][r] = 0.0f;

    auto load_tile = [&](int buf, int k0) {
#pragma unroll
        for (int f = tid; f < 512; f += 256) {          // A: 128x16 = 512 float4
            int r = f >> 2, cg = f & 3;
            cp_async16(&As[buf][r * AS_STRIDE + cg * 4],
                       A + (size_t)(bm + r) * K + k0 + cg * 4);
        }
#pragma unroll
        for (int f = tid; f < 512; f += 256) {          // B: 16x128 = 512 float4
            int r = f >> 5, c4 = f & 31;
            cp_async16(&Bs[buf][r * BS_STRIDE + c4 * 4],
                       B + (size_t)(k0 + r) * N + bn + c4 * 4);
        }
        cp_commit();
    };

    load_tile(0, 0);
    cp_wait0();
    __syncthreads();

    const int KT = K >> 4;
    int buf = 0;
#pragma unroll 1
    for (int kt = 0; kt < KT; kt++) {
        if (kt + 1 < KT) load_tile(buf ^ 1, (kt + 1) * 16);

        const float* Ab = &As[buf][0];
        const float* Bb = &Bs[buf][0];
#pragma unroll
        for (int ks = 0; ks < 16; ks += 8) {
            uint32_t af[4][4], bf[4][2];
#pragma unroll
            for (int mt = 0; mt < 4; mt++) {
                const int m0 = wm * 64 + mt * 16;
                af[mt][0] = f2tf32(Ab[(m0 + g)     * AS_STRIDE + ks + t]);
                af[mt][1] = f2tf32(Ab[(m0 + g + 8) * AS_STRIDE + ks + t]);
                af[mt][2] = f2tf32(Ab[(m0 + g)     * AS_STRIDE + ks + t + 4]);
                af[mt][3] = f2tf32(Ab[(m0 + g + 8) * AS_STRIDE + ks + t + 4]);
            }
#pragma unroll
            for (int nt = 0; nt < 4; nt++) {
                const int n0 = wn * 32 + nt * 8;
                bf[nt][0] = f2tf32(Bb[(ks + t)     * BS_STRIDE + n0 + g]);
                bf[nt][1] = f2tf32(Bb[(ks + t + 4) * BS_STRIDE + n0 + g]);
            }
#pragma unroll
            for (int mt = 0; mt < 4; mt++)
#pragma unroll
                for (int nt = 0; nt < 4; nt++)
                    mma_tf32(acc[mt][nt][0], acc[mt][nt][1], acc[mt][nt][2], acc[mt][nt][3],
                             af[mt][0], af[mt][1], af[mt][2], af[mt][3],
                             bf[nt][0], bf[nt][1]);
        }

        if (kt + 1 < KT) cp_wait0();
        __syncthreads();
        buf ^= 1;
    }

    // Epilogue: bias + store (float2)
#pragma unroll
    for (int mt = 0; mt < 4; mt++) {
        const int row0 = bm + wm * 64 + mt * 16 + g;
#pragma unroll
        for (int nt = 0; nt < 4; nt++) {
            const int col = bn + wn * 32 + nt * 8 + 2 * t;
            const float bx = bias[col], by = bias[col + 1];
            float2 v0 = make_float2(acc[mt][nt][0] + bx, acc[mt][nt][1] + by);
            float2 v1 = make_float2(acc[mt][nt][2] + bx, acc[mt][nt][3] + by);
            *reinterpret_cast<float2*>(&C[(size_t)row0 * N + col]) = v0;
            *reinterpret_cast<float2*>(&C[(size_t)(row0 + 8) * N + col]) = v1;
        }
    }
}

// ---------------------------------------------------------------------------
// Flash attention, TF32 mma. grid=(T/64, H, B), 128 threads (4 warps).
// Warp w owns q rows [16w, 16w+16). KV tile = 64. HD=64.
// ---------------------------------------------------------------------------
#define KS_STRIDE 68    // HD + 4 (frag bank: 4g+t all-distinct)

__global__ __launch_bounds__(128)
void attn_tf32_kernel(const float* __restrict__ qkv, float* __restrict__ out) {
    __shared__ float Ks[64 * KS_STRIDE];   // also used to stage Q
    __shared__ float Vt[64 * KS_STRIDE];   // V transposed: [d][kv]

    const int tid  = threadIdx.x;
    const int lane = tid & 31;
    const int w    = tid >> 5;
    const int g    = lane >> 2;
    const int t    = lane & 3;
    const int qt   = blockIdx.x;
    const int h    = blockIdx.y;
    const int b    = blockIdx.z;
    const float scale = 0.125f;   // 1/sqrt(64)

    const size_t base = (size_t)b * Tseq * C3 + (size_t)h * HD;

    // ---- Stage Q (64x64) into Ks region, build register Q fragments ----
    for (int f = tid; f < 64 * 16; f += 128) {
        int r = f >> 4, dg = f & 15;
        *reinterpret_cast<float4*>(&Ks[r * KS_STRIDE + dg * 4]) =
            *reinterpret_cast<const float4*>(&qkv[base + (size_t)(qt * 64 + r) * C3 + dg * 4]);
    }
    __syncthreads();

    uint32_t qf[8][4];
    {
        const int r0 = w * 16 + g;
#pragma unroll
        for (int kc = 0; kc < 8; kc++) {
            qf[kc][0] = f2tf32(scale * Ks[(r0)     * KS_STRIDE + kc * 8 + t]);
            qf[kc][1] = f2tf32(scale * Ks[(r0 + 8) * KS_STRIDE + kc * 8 + t]);
            qf[kc][2] = f2tf32(scale * Ks[(r0)     * KS_STRIDE + kc * 8 + t + 4]);
            qf[kc][3] = f2tf32(scale * Ks[(r0 + 8) * KS_STRIDE + kc * 8 + t + 4]);
        }
    }
    __syncthreads();

    float oa[8][4];
#pragma unroll
    for (int i = 0; i < 8; i++)
#pragma unroll
        for (int j = 0; j < 4; j++) oa[i][j] = 0.0f;

    float m0r = -1e30f, m1r = -1e30f, l0 = 0.0f, l1 = 0.0f;
    const int q0g = qt * 64 + w * 16 + g;
    const int q1g = q0g + 8;

    for (int kt = 0; kt <= qt; kt++) {
        // ---- Load K tile and V tile (transposed) ----
        for (int f = tid; f < 1024; f += 128) {
            int r = f >> 4, dg = f & 15;
            size_t off = base + (size_t)(kt * 64 + r) * C3 + dg * 4;
            *reinterpret_cast<float4*>(&Ks[r * KS_STRIDE + dg * 4]) =
                *reinterpret_cast<const float4*>(&qkv[off + Cdim]);
            float4 v = *reinterpret_cast<const float4*>(&qkv[off + 2 * Cdim]);
            float vv[4] = {v.x, v.y, v.z, v.w};
            // j-rotation lowers STS conflict from 8-way to 4-way
#pragma unroll
            for (int jj = 0; jj < 4; jj++) {
                int j = (jj + dg) & 3;
                Vt[(4 * dg + j) * KS_STRIDE + r] = vv[j];
            }
        }
        __syncthreads();

        // ---- S = (Q*scale) @ K^T ----
        float s[8][4];
#pragma unroll
        for (int i = 0; i < 8; i++)
#pragma unroll
            for (int j = 0; j < 4; j++) s[i][j] = 0.0f;

#pragma unroll
        for (int kc = 0; kc < 8; kc++) {          // d chunks
#pragma unroll
            for (int nt = 0; nt < 8; nt++) {      // kv n-tiles
                uint32_t b0 = f2tf32(Ks[(nt * 8 + g) * KS_STRIDE + kc * 8 + t]);
                uint32_t b1 = f2tf32(Ks[(nt * 8 + g) * KS_STRIDE + kc * 8 + t + 4]);
                mma_tf32(s[nt][0], s[nt][1], s[nt][2], s[nt][3],
                         qf[kc][0], qf[kc][1], qf[kc][2], qf[kc][3], b0, b1);
            }
        }

        // ---- causal mask (only diagonal tile) ----
        if (kt == qt) {
#pragma unroll
            for (int nt = 0; nt < 8; nt++) {
                const int k0 = kt * 64 + nt * 8 + 2 * t;
                if (k0 > q0g)     s[nt][0] = -1e30f;
                if (k0 + 1 > q0g) s[nt][1] = -1e30f;
                if (k0 > q1g)     s[nt][2] = -1e30f;
                if (k0 + 1 > q1g) s[nt][3] = -1e30f;
            }
        }

        // ---- streaming softmax (registers + quad shuffles) ----
        float rmax0 = -1e30f, rmax1 = -1e30f;
#pragma unroll
        for (int nt = 0; nt < 8; nt++) {
            rmax0 = fmaxf(rmax0, fmaxf(s[nt][0], s[nt][1]));
            rmax1 = fmaxf(rmax1, fmaxf(s[nt][2], s[nt][3]));
        }
        rmax0 = fmaxf(rmax0, __shfl_xor_sync(0xffffffffu, rmax0, 1));
        rmax0 = fmaxf(rmax0, __shfl_xor_sync(0xffffffffu, rmax0, 2));
        rmax1 = fmaxf(rmax1, __shfl_xor_sync(0xffffffffu, rmax1, 1));
        rmax1 = fmaxf(rmax1, __shfl_xor_sync(0xffffffffu, rmax1, 2));

        const float mn0 = fmaxf(m0r, rmax0);
        const float mn1 = fmaxf(m1r, rmax1);
        const float al0 = __expf(m0r - mn0);
        const float al1 = __expf(m1r - mn1);
        m0r = mn0; m1r = mn1;

        float rs0 = 0.0f, rs1 = 0.0f;
#pragma unroll
        for (int nt = 0; nt < 8; nt++) {
            s[nt][0] = __expf(s[nt][0] - mn0);
            s[nt][1] = __expf(s[nt][1] - mn0);
            s[nt][2] = __expf(s[nt][2] - mn1);
            s[nt][3] = __expf(s[nt][3] - mn1);
            rs0 += s[nt][0] + s[nt][1];
            rs1 += s[nt][2] + s[nt][3];
        }
        rs0 += __shfl_xor_sync(0xffffffffu, rs0, 1);
        rs0 += __shfl_xor_sync(0xffffffffu, rs0, 2);
        rs1 += __shfl_xor_sync(0xffffffffu, rs1, 1);
        rs1 += __shfl_xor_sync(0xffffffffu, rs1, 2);
        l0 = l0 * al0 + rs0;
        l1 = l1 * al1 + rs1;

        // rescale O accumulator
#pragma unroll
        for (int dt = 0; dt < 8; dt++) {
            oa[dt][0] *= al0; oa[dt][1] *= al0;
            oa[dt][2] *= al1; oa[dt][3] *= al1;
        }

        // ---- O += P @ V : build P A-frags via lane shuffles, mma against Vt ----
        const int s0l = (lane & ~3) | (t >> 1);
        const int s1l = s0l + 2;
        const bool odd = (t & 1) != 0;
#pragma unroll
        for (int kc = 0; kc < 8; kc++) {          // kv chunks
            float v00 = __shfl_sync(0xffffffffu, s[kc][0], s0l);
            float v01 = __shfl_sync(0xffffffffu, s[kc][1], s0l);
            float v02 = __shfl_sync(0xffffffffu, s[kc][2], s0l);
            float v03 = __shfl_sync(0xffffffffu, s[kc][3], s0l);
            float v10 = __shfl_sync(0xffffffffu, s[kc][0], s1l);
            float v11 = __shfl_sync(0xffffffffu, s[kc][1], s1l);
            float v12 = __shfl_sync(0xffffffffu, s[kc][2], s1l);
            float v13 = __shfl_sync(0xffffffffu, s[kc][3], s1l);
            uint32_t p0 = f2tf32(odd ? v01 : v00);
            uint32_t p1 = f2tf32(odd ? v03 : v02);
            uint32_t p2 = f2tf32(odd ? v11 : v10);
            uint32_t p3 = f2tf32(odd ? v13 : v12);
#pragma unroll
            for (int dt = 0; dt < 8; dt++) {
                uint32_t b0 = f2tf32(Vt[(dt * 8 + g) * KS_STRIDE + kc * 8 + t]);
                uint32_t b1 = f2tf32(Vt[(dt * 8 + g) * KS_STRIDE + kc * 8 + t + 4]);
                mma_tf32(oa[dt][0], oa[dt][1], oa[dt][2], oa[dt][3],
                         p0, p1, p2, p3, b0, b1);
            }
        }
        __syncthreads();
    }

    // ---- finalize and write [B,T,C] ----
    const float il0 = 1.0f / l0;
    const float il1 = 1.0f / l1;
    const size_t ob = (size_t)b * Tseq * Cdim + (size_t)h * HD;
    const int r0 = qt * 64 + w * 16 + g;
#pragma unroll
    for (int dt = 0; dt < 8; dt++) {
        const int col = dt * 8 + 2 * t;
        float2 o0 = make_float2(oa[dt][0] * il0, oa[dt][1] * il0);
        float2 o1 = make_float2(oa[dt][2] * il1, oa[dt][3] * il1);
        *reinterpret_cast<float2*>(&out[ob + (size_t)r0 * Cdim + col]) = o0;
        *reinterpret_cast<float2*>(&out[ob + (size_t)(r0 + 8) * Cdim + col]) = o1;
    }
}

// ---------------------------------------------------------------------------
// Launch
// ---------------------------------------------------------------------------
extern "C" void kernel_launch(void* const* d_in, const int* in_sizes, int n_in,
                              void* d_out, int out_size) {
    const float* x      = (const float*)d_in[0];
    const float* w_attn = (const float*)d_in[1];
    const float* b_attn = (const float*)d_in[2];
    const float* w_proj = (const float*)d_in[3];
    const float* b_proj = (const float*)d_in[4];
    float* out = (float*)d_out;

    float* qkv = nullptr;
    float* att = nullptr;
    cudaGetSymbolAddress((void**)&qkv, g_qkv);
    cudaGetSymbolAddress((void**)&att, g_att);

    const int M = Bsz * Tseq;  // 4096

    {   // qkv = x @ w_attn + b_attn  [4096,3072]
        dim3 grid(C3 / 128, M / 128);
        gemm_tf32_kernel<<<grid, 256>>>(x, w_attn, b_attn, qkv, M, C3, Cdim);
    }
    {   // attention
        dim3 grid(Tseq / 64, Hn, Bsz);
        attn_tf32_kernel<<<grid, 128>>>(qkv, att);
    }
    {   // out = att @ w_proj + b_proj  [4096,1024]
        dim3 grid(Cdim / 128, M / 128);
        gemm_tf32_kernel<<<grid, 256>>>(att, w_proj, b_proj, out, M, Cdim, Cdim);
    }
}

// round 4
// speedup vs baseline: 6.5829x; 2.3348x over previous
#include <cuda_runtime.h>
#include <cuda_fp16.h>
#include <cstdint>

// Problem constants
#define Bsz 2
#define Tseq 2048
#define Cdim 1024
#define Hn 16
#define HD 64
#define C3 (3 * Cdim)

// Scratch (allocation-free rule: __device__ globals), fp16 intermediates
__device__ __half g_qkv[Bsz * Tseq * C3];    // [B,T,3C]
__device__ __half g_att[Bsz * Tseq * Cdim];  // [B,T,C]
__device__ __half g_xh[Bsz * Tseq * Cdim];   // x in fp16
__device__ __half g_waT[C3 * Cdim];          // w_attn^T [3C,C]
__device__ __half g_wpT[Cdim * Cdim];        // w_proj^T [C,C]

// ---------------------------------------------------------------------------
// helpers
// ---------------------------------------------------------------------------
__device__ __forceinline__ uint32_t smem_u32(const void* p) {
    return (uint32_t)__cvta_generic_to_shared(p);
}
__device__ __forceinline__ void cp_async16(void* dst, const void* src) {
    asm volatile("cp.async.ca.shared.global [%0], [%1], 16;"
                 :: "r"(smem_u32(dst)), "l"(src));
}
__device__ __forceinline__ void cp_commit() { asm volatile("cp.async.commit_group;"); }

__device__ __forceinline__ void ldsm_x4(uint32_t& r0, uint32_t& r1, uint32_t& r2, uint32_t& r3,
                                        uint32_t addr) {
    asm volatile("ldmatrix.sync.aligned.m8n8.x4.shared.b16 {%0,%1,%2,%3}, [%4];"
                 : "=r"(r0), "=r"(r1), "=r"(r2), "=r"(r3) : "r"(addr));
}
__device__ __forceinline__ void ldsm_x4_t(uint32_t& r0, uint32_t& r1, uint32_t& r2, uint32_t& r3,
                                          uint32_t addr) {
    asm volatile("ldmatrix.sync.aligned.m8n8.x4.trans.shared.b16 {%0,%1,%2,%3}, [%4];"
                 : "=r"(r0), "=r"(r1), "=r"(r2), "=r"(r3) : "r"(addr));
}

__device__ __forceinline__ void mma_f16(float& c0, float& c1, float& c2, float& c3,
                                        uint32_t a0, uint32_t a1, uint32_t a2, uint32_t a3,
                                        uint32_t b0, uint32_t b1) {
    asm volatile(
        "mma.sync.aligned.m16n8k16.row.col.f32.f16.f16.f32 "
        "{%0,%1,%2,%3}, {%4,%5,%6,%7}, {%8,%9}, {%0,%1,%2,%3};"
        : "+f"(c0), "+f"(c1), "+f"(c2), "+f"(c3)
        : "r"(a0), "r"(a1), "r"(a2), "r"(a3), "r"(b0), "r"(b1));
}

__device__ __forceinline__ uint32_t pack_h2(float lo, float hi) {
    __half2 h = __floats2half2_rn(lo, hi);
    return *reinterpret_cast<uint32_t*>(&h);
}

// ---------------------------------------------------------------------------
// Pre-passes
// ---------------------------------------------------------------------------
__global__ void f32_to_f16_kernel(const float* __restrict__ in, __half* __restrict__ outp) {
    const int i = (blockIdx.x * blockDim.x + threadIdx.x) * 4;
    float4 v = *reinterpret_cast<const float4*>(in + i);
    __half2 h0 = __floats2half2_rn(v.x, v.y);
    __half2 h1 = __floats2half2_rn(v.z, v.w);
    *reinterpret_cast<__half2*>(outp + i) = h0;
    *reinterpret_cast<__half2*>(outp + i + 2) = h1;
}

// W [K,N] f32 row-major -> WT [N,K] half row-major
__global__ __launch_bounds__(256)
void transpose_f16_kernel(const float* __restrict__ W, __half* __restrict__ WT,
                          int K, int N) {
    __shared__ float tile[32][33];
    const int bx = blockIdx.x * 32;   // n
    const int by = blockIdx.y * 32;   // k
    const int tx = threadIdx.x, ty = threadIdx.y;
#pragma unroll
    for (int i = 0; i < 32; i += 8)
        tile[ty + i][tx] = W[(size_t)(by + ty + i) * N + bx + tx];
    __syncthreads();
#pragma unroll
    for (int i = 0; i < 32; i += 8)
        WT[(size_t)(bx + ty + i) * K + by + tx] = __float2half_rn(tile[tx][ty + i]);
}

// ---------------------------------------------------------------------------
// FP16 GEMM: C[M,N] = A[M,K](half) @ BT[N,K](half)^T + bias[N]
// 128x128 block, BK=32, 256 threads (8 warps 2x4), warp tile 64x32,
// cp.async double buffer, ldmatrix fragment loads.
// ---------------------------------------------------------------------------
template <bool OUT_HALF>
__global__ __launch_bounds__(256, 2)
void gemm_f16_kernel(const __half* __restrict__ A, const __half* __restrict__ BT,
                     const float* __restrict__ bias, void* __restrict__ Cout,
                     int M, int N, int K) {
    __shared__ __half As[2][128][40];   // BK=32 + 8 pad (80B row stride)
    __shared__ __half Bs[2][128][40];

    const int tid  = threadIdx.x;
    const int lane = tid & 31;
    const int wid  = tid >> 5;
    const int wm   = wid >> 2;
    const int wn   = wid & 3;
    const int g    = lane >> 2;
    const int t    = lane & 3;
    const int bm   = blockIdx.y * 128;
    const int bn   = blockIdx.x * 128;

    float acc[4][4][4];
#pragma unroll
    for (int i = 0; i < 4; i++)
#pragma unroll
        for (int j = 0; j < 4; j++)
#pragma unroll
            for (int r = 0; r < 4; r++) acc[i][j][r] = 0.0f;

    // ldmatrix lane addressing (constant per thread)
    const int a_row = lane & 15;
    const int a_col = (lane >> 4) << 3;
    const int b_row = ((lane >> 4) << 3) + (lane & 7);
    const int b_col = ((lane >> 3) & 1) << 3;

    auto fill = [&](int buf, int k0) {
#pragma unroll
        for (int f = tid; f < 1024; f += 256) {
            const int i = f & 511;
            const int r = i >> 2, c = i & 3;
            if (f < 512)
                cp_async16(&As[buf][r][c * 8], A + (size_t)(bm + r) * K + k0 + c * 8);
            else
                cp_async16(&Bs[buf][r][c * 8], BT + (size_t)(bn + r) * K + k0 + c * 8);
        }
        cp_commit();
    };

    fill(0, 0);
    asm volatile("cp.async.wait_group 0;" ::: "memory");
    __syncthreads();

    const int KT = K >> 5;
    int buf = 0;
#pragma unroll 1
    for (int kt = 0; kt < KT; kt++) {
        if (kt + 1 < KT) fill(buf ^ 1, (kt + 1) * 32);

#pragma unroll
        for (int ks8 = 0; ks8 < 2; ks8++) {
            const int ks = ks8 * 16;
            uint32_t af[4][4], bf[4][2];
#pragma unroll
            for (int mt = 0; mt < 4; mt++) {
                const int m0 = wm * 64 + mt * 16;
                ldsm_x4(af[mt][0], af[mt][1], af[mt][2], af[mt][3],
                        smem_u32(&As[buf][m0 + a_row][ks + a_col]));
            }
#pragma unroll
            for (int p = 0; p < 2; p++) {
                const int n0 = wn * 32 + p * 16;
                ldsm_x4(bf[2 * p][0], bf[2 * p][1], bf[2 * p + 1][0], bf[2 * p + 1][1],
                        smem_u32(&Bs[buf][n0 + b_row][ks + b_col]));
            }
#pragma unroll
            for (int mt = 0; mt < 4; mt++)
#pragma unroll
                for (int nt = 0; nt < 4; nt++)
                    mma_f16(acc[mt][nt][0], acc[mt][nt][1], acc[mt][nt][2], acc[mt][nt][3],
                            af[mt][0], af[mt][1], af[mt][2], af[mt][3],
                            bf[nt][0], bf[nt][1]);
        }

        if (kt + 1 < KT) asm volatile("cp.async.wait_group 0;" ::: "memory");
        __syncthreads();
        buf ^= 1;
    }

    // Epilogue
#pragma unroll
    for (int mt = 0; mt < 4; mt++) {
        const int row0 = bm + wm * 64 + mt * 16 + g;
#pragma unroll
        for (int nt = 0; nt < 4; nt++) {
            const int col = bn + wn * 32 + nt * 8 + 2 * t;
            const float bx = bias[col], by = bias[col + 1];
            const float v00 = acc[mt][nt][0] + bx, v01 = acc[mt][nt][1] + by;
            const float v10 = acc[mt][nt][2] + bx, v11 = acc[mt][nt][3] + by;
            if (OUT_HALF) {
                __half* C = (__half*)Cout;
                *reinterpret_cast<uint32_t*>(&C[(size_t)row0 * N + col]) = pack_h2(v00, v01);
                *reinterpret_cast<uint32_t*>(&C[(size_t)(row0 + 8) * N + col]) = pack_h2(v10, v11);
            } else {
                float* C = (float*)Cout;
                *reinterpret_cast<float2*>(&C[(size_t)row0 * N + col]) = make_float2(v00, v01);
                *reinterpret_cast<float2*>(&C[(size_t)(row0 + 8) * N + col]) = make_float2(v10, v11);
            }
        }
    }
}

// ---------------------------------------------------------------------------
// FP16 flash attention. grid=(T/64, H, B), 128 threads (4 warps).
// Warp w owns q rows [16w,16w+16). KV tile 64. HD=64.
// K frags via ldmatrix, V frags via ldmatrix.trans (no smem transpose),
// P C-frags are directly reusable as A-frags (no shuffles).
// ---------------------------------------------------------------------------
#define KSW 72   // 64 + 8 halves (144B row stride -> conflict-free ldmatrix)

__global__ __launch_bounds__(128)
void attn_f16_kernel(const __half* __restrict__ qkv, __half* __restrict__ out) {
    __shared__ __half Ks[64][KSW];   // K tile (also stages Q)
    __shared__ __half Vs[64][KSW];   // V tile (row-major [kv][d])

    const int tid  = threadIdx.x;
    const int lane = tid & 31;
    const int w    = tid >> 5;
    const int g    = lane >> 2;
    const int t    = lane & 3;
    const int qt   = (int)gridDim.x - 1 - (int)blockIdx.x;  // big tiles first
    const int h    = blockIdx.y;
    const int b    = blockIdx.z;

    const size_t base = (size_t)b * Tseq * C3 + (size_t)h * HD;

    const int a_row = lane & 15;
    const int a_col = (lane >> 4) << 3;
    const int b_row = ((lane >> 4) << 3) + (lane & 7);
    const int b_col = ((lane >> 3) & 1) << 3;

    // ---- Stage Q into Ks, build Q A-frags ----
    for (int f = tid; f < 512; f += 128) {         // 64 rows x 4 chunks of 16B
        const int r = f >> 3, c = f & 7;
        *reinterpret_cast<uint4*>(&Ks[r][c * 8]) =
            *reinterpret_cast<const uint4*>(&qkv[base + (size_t)(qt * 64 + r) * C3 + c * 8]);
    }
    __syncthreads();

    uint32_t qf[4][4];
#pragma unroll
    for (int kc = 0; kc < 4; kc++)
        ldsm_x4(qf[kc][0], qf[kc][1], qf[kc][2], qf[kc][3],
                smem_u32(&Ks[w * 16 + a_row][kc * 16 + a_col]));
    __syncthreads();

    float oa[8][4];
#pragma unroll
    for (int i = 0; i < 8; i++)
#pragma unroll
        for (int j = 0; j < 4; j++) oa[i][j] = 0.0f;

    float m0r = -1e30f, m1r = -1e30f, l0 = 0.0f, l1 = 0.0f;
    const int q0g = qt * 64 + w * 16 + g;
    const int q1g = q0g + 8;

    for (int kt = 0; kt <= qt; kt++) {
        // ---- Load K and V tiles ----
        for (int f = tid; f < 512; f += 128) {
            const int r = f >> 3, c = f & 7;
            const size_t off = base + (size_t)(kt * 64 + r) * C3 + c * 8;
            *reinterpret_cast<uint4*>(&Ks[r][c * 8]) =
                *reinterpret_cast<const uint4*>(&qkv[off + Cdim]);
            *reinterpret_cast<uint4*>(&Vs[r][c * 8]) =
                *reinterpret_cast<const uint4*>(&qkv[off + 2 * Cdim]);
        }
        __syncthreads();

        // ---- S = Q @ K^T ----
        float s[8][4];
#pragma unroll
        for (int i = 0; i < 8; i++)
#pragma unroll
            for (int j = 0; j < 4; j++) s[i][j] = 0.0f;

#pragma unroll
        for (int kc = 0; kc < 4; kc++) {
#pragma unroll
            for (int p = 0; p < 4; p++) {
                uint32_t b0a, b1a, b0b, b1b;
                ldsm_x4(b0a, b1a, b0b, b1b,
                        smem_u32(&Ks[p * 16 + b_row][kc * 16 + b_col]));
                mma_f16(s[2 * p][0], s[2 * p][1], s[2 * p][2], s[2 * p][3],
                        qf[kc][0], qf[kc][1], qf[kc][2], qf[kc][3], b0a, b1a);
                mma_f16(s[2 * p + 1][0], s[2 * p + 1][1], s[2 * p + 1][2], s[2 * p + 1][3],
                        qf[kc][0], qf[kc][1], qf[kc][2], qf[kc][3], b0b, b1b);
            }
        }

        // scale
#pragma unroll
        for (int nt = 0; nt < 8; nt++)
#pragma unroll
            for (int j = 0; j < 4; j++) s[nt][j] *= 0.125f;

        // causal mask (diagonal tile only)
        if (kt == qt) {
#pragma unroll
            for (int nt = 0; nt < 8; nt++) {
                const int k0 = kt * 64 + nt * 8 + 2 * t;
                if (k0 > q0g)     s[nt][0] = -1e30f;
                if (k0 + 1 > q0g) s[nt][1] = -1e30f;
                if (k0 > q1g)     s[nt][2] = -1e30f;
                if (k0 + 1 > q1g) s[nt][3] = -1e30f;
            }
        }

        // ---- streaming softmax ----
        float rmax0 = -1e30f, rmax1 = -1e30f;
#pragma unroll
        for (int nt = 0; nt < 8; nt++) {
            rmax0 = fmaxf(rmax0, fmaxf(s[nt][0], s[nt][1]));
            rmax1 = fmaxf(rmax1, fmaxf(s[nt][2], s[nt][3]));
        }
        rmax0 = fmaxf(rmax0, __shfl_xor_sync(0xffffffffu, rmax0, 1));
        rmax0 = fmaxf(rmax0, __shfl_xor_sync(0xffffffffu, rmax0, 2));
        rmax1 = fmaxf(rmax1, __shfl_xor_sync(0xffffffffu, rmax1, 1));
        rmax1 = fmaxf(rmax1, __shfl_xor_sync(0xffffffffu, rmax1, 2));

        const float mn0 = fmaxf(m0r, rmax0);
        const float mn1 = fmaxf(m1r, rmax1);
        const float al0 = __expf(m0r - mn0);
        const float al1 = __expf(m1r - mn1);
        m0r = mn0; m1r = mn1;

        float rs0 = 0.0f, rs1 = 0.0f;
#pragma unroll
        for (int nt = 0; nt < 8; nt++) {
            s[nt][0] = __expf(s[nt][0] - mn0);
            s[nt][1] = __expf(s[nt][1] - mn0);
            s[nt][2] = __expf(s[nt][2] - mn1);
            s[nt][3] = __expf(s[nt][3] - mn1);
            rs0 += s[nt][0] + s[nt][1];
            rs1 += s[nt][2] + s[nt][3];
        }
        rs0 += __shfl_xor_sync(0xffffffffu, rs0, 1);
        rs0 += __shfl_xor_sync(0xffffffffu, rs0, 2);
        rs1 += __shfl_xor_sync(0xffffffffu, rs1, 1);
        rs1 += __shfl_xor_sync(0xffffffffu, rs1, 2);
        l0 = l0 * al0 + rs0;
        l1 = l1 * al1 + rs1;

#pragma unroll
        for (int dt = 0; dt < 8; dt++) {
            oa[dt][0] *= al0; oa[dt][1] *= al0;
            oa[dt][2] *= al1; oa[dt][3] *= al1;
        }

        // ---- O += P @ V : P C-frags -> A-frags directly; V via ldmatrix.trans ----
#pragma unroll
        for (int j = 0; j < 4; j++) {   // kv k16 steps
            const uint32_t a0 = pack_h2(s[2 * j][0], s[2 * j][1]);
            const uint32_t a1 = pack_h2(s[2 * j][2], s[2 * j][3]);
            const uint32_t a2 = pack_h2(s[2 * j + 1][0], s[2 * j + 1][1]);
            const uint32_t a3 = pack_h2(s[2 * j + 1][2], s[2 * j + 1][3]);
#pragma unroll
            for (int dp = 0; dp < 4; dp++) {   // pairs of d-tiles
                uint32_t b0a, b1a, b0b, b1b;
                ldsm_x4_t(b0a, b1a, b0b, b1b,
                          smem_u32(&Vs[j * 16 + a_row][dp * 16 + a_col]));
                mma_f16(oa[2 * dp][0], oa[2 * dp][1], oa[2 * dp][2], oa[2 * dp][3],
                        a0, a1, a2, a3, b0a, b1a);
                mma_f16(oa[2 * dp + 1][0], oa[2 * dp + 1][1], oa[2 * dp + 1][2], oa[2 * dp + 1][3],
                        a0, a1, a2, a3, b0b, b1b);
            }
        }
        __syncthreads();
    }

    // ---- finalize, write half [B,T,C] ----
    const float il0 = 1.0f / l0;
    const float il1 = 1.0f / l1;
    const size_t ob = (size_t)b * Tseq * Cdim + (size_t)h * HD;
    const int r0 = qt * 64 + w * 16 + g;
#pragma unroll
    for (int dt = 0; dt < 8; dt++) {
        const int col = dt * 8 + 2 * t;
        *reinterpret_cast<uint32_t*>(&out[ob + (size_t)r0 * Cdim + col]) =
            pack_h2(oa[dt][0] * il0, oa[dt][1] * il0);
        *reinterpret_cast<uint32_t*>(&out[ob + (size_t)(r0 + 8) * Cdim + col]) =
            pack_h2(oa[dt][2] * il1, oa[dt][3] * il1);
    }
}

// ---------------------------------------------------------------------------
// Launch
// ---------------------------------------------------------------------------
extern "C" void kernel_launch(void* const* d_in, const int* in_sizes, int n_in,
                              void* d_out, int out_size) {
    const float* x      = (const float*)d_in[0];
    const float* w_attn = (const float*)d_in[1];
    const float* b_attn = (const float*)d_in[2];
    const float* w_proj = (const float*)d_in[3];
    const float* b_proj = (const float*)d_in[4];
    float* out = (float*)d_out;

    __half *qkv, *att, *xh, *waT, *wpT;
    cudaGetSymbolAddress((void**)&qkv, g_qkv);
    cudaGetSymbolAddress((void**)&att, g_att);
    cudaGetSymbolAddress((void**)&xh,  g_xh);
    cudaGetSymbolAddress((void**)&waT, g_waT);
    cudaGetSymbolAddress((void**)&wpT, g_wpT);

    const int M = Bsz * Tseq;  // 4096

    // Pre-passes: x -> fp16; weights -> transposed fp16 [N,K]
    f32_to_f16_kernel<<<(M * Cdim) / (256 * 4), 256>>>(x, xh);
    {
        dim3 blk(32, 8);
        transpose_f16_kernel<<<dim3(C3 / 32, Cdim / 32), blk>>>(w_attn, waT, Cdim, C3);
        transpose_f16_kernel<<<dim3(Cdim / 32, Cdim / 32), blk>>>(w_proj, wpT, Cdim, Cdim);
    }

    // 1) qkv = x @ w_attn + b_attn   [4096,3072] (half out)
    gemm_f16_kernel<true><<<dim3(C3 / 128, M / 128), 256>>>(
        xh, waT, b_attn, qkv, M, C3, Cdim);

    // 2) attention -> g_att (half)
    attn_f16_kernel<<<dim3(Tseq / 64, Hn, Bsz), 128>>>(qkv, att);

    // 3) out = att @ w_proj + b_proj  [4096,1024] (float out)
    gemm_f16_kernel<false><<<dim3(Cdim / 128, M / 128), 256>>>(
        att, wpT, b_proj, out, M, Cdim, Cdim);
}

// round 5
// speedup vs baseline: 6.6481x; 1.0099x over previous
#include <cuda_runtime.h>
#include <cuda_fp16.h>
#include <cstdint>

// Problem constants
#define Bsz 2
#define Tseq 2048
#define Cdim 1024
#define Hn 16
#define HD 64
#define C3 (3 * Cdim)

// Scratch (allocation-free rule: __device__ globals), fp16 intermediates
__device__ __half g_qkv[Bsz * Tseq * C3];    // [B,T,3C]
__device__ __half g_att[Bsz * Tseq * Cdim];  // [B,T,C]
__device__ __half g_xh[Bsz * Tseq * Cdim];   // x in fp16
__device__ __half g_waT[C3 * Cdim];          // w_attn^T [3C,C]
__device__ __half g_wpT[Cdim * Cdim];        // w_proj^T [C,C]

// ---------------------------------------------------------------------------
// helpers
// ---------------------------------------------------------------------------
__device__ __forceinline__ uint32_t smem_u32(const void* p) {
    return (uint32_t)__cvta_generic_to_shared(p);
}
__device__ __forceinline__ void cp_async16(void* dst, const void* src) {
    asm volatile("cp.async.ca.shared.global [%0], [%1], 16;"
                 :: "r"(smem_u32(dst)), "l"(src));
}
__device__ __forceinline__ void cp_commit() { asm volatile("cp.async.commit_group;"); }

__device__ __forceinline__ void ldsm_x4(uint32_t& r0, uint32_t& r1, uint32_t& r2, uint32_t& r3,
                                        uint32_t addr) {
    asm volatile("ldmatrix.sync.aligned.m8n8.x4.shared.b16 {%0,%1,%2,%3}, [%4];"
                 : "=r"(r0), "=r"(r1), "=r"(r2), "=r"(r3) : "r"(addr));
}
__device__ __forceinline__ void ldsm_x4_t(uint32_t& r0, uint32_t& r1, uint32_t& r2, uint32_t& r3,
                                          uint32_t addr) {
    asm volatile("ldmatrix.sync.aligned.m8n8.x4.trans.shared.b16 {%0,%1,%2,%3}, [%4];"
                 : "=r"(r0), "=r"(r1), "=r"(r2), "=r"(r3) : "r"(addr));
}

__device__ __forceinline__ void mma_f16(float& c0, float& c1, float& c2, float& c3,
                                        uint32_t a0, uint32_t a1, uint32_t a2, uint32_t a3,
                                        uint32_t b0, uint32_t b1) {
    asm volatile(
        "mma.sync.aligned.m16n8k16.row.col.f32.f16.f16.f32 "
        "{%0,%1,%2,%3}, {%4,%5,%6,%7}, {%8,%9}, {%0,%1,%2,%3};"
        : "+f"(c0), "+f"(c1), "+f"(c2), "+f"(c3)
        : "r"(a0), "r"(a1), "r"(a2), "r"(a3), "r"(b0), "r"(b1));
}

__device__ __forceinline__ uint32_t pack_h2(float lo, float hi) {
    __half2 h = __floats2half2_rn(lo, hi);
    return *reinterpret_cast<uint32_t*>(&h);
}

// ---------------------------------------------------------------------------
// Pre-passes
// ---------------------------------------------------------------------------
__global__ void f32_to_f16_kernel(const float* __restrict__ in, __half* __restrict__ outp) {
    const int i = (blockIdx.x * blockDim.x + threadIdx.x) * 4;
    float4 v = *reinterpret_cast<const float4*>(in + i);
    *reinterpret_cast<__half2*>(outp + i) = __floats2half2_rn(v.x, v.y);
    *reinterpret_cast<__half2*>(outp + i + 2) = __floats2half2_rn(v.z, v.w);
}

// W [K,N] f32 row-major -> WT [N,K] half row-major
__global__ __launch_bounds__(256)
void transpose_f16_kernel(const float* __restrict__ W, __half* __restrict__ WT,
                          int K, int N) {
    __shared__ float tile[32][33];
    const int bx = blockIdx.x * 32;
    const int by = blockIdx.y * 32;
    const int tx = threadIdx.x, ty = threadIdx.y;
#pragma unroll
    for (int i = 0; i < 32; i += 8)
        tile[ty + i][tx] = W[(size_t)(by + ty + i) * N + bx + tx];
    __syncthreads();
#pragma unroll
    for (int i = 0; i < 32; i += 8)
        WT[(size_t)(bx + ty + i) * K + by + tx] = __float2half_rn(tile[tx][ty + i]);
}

// ---------------------------------------------------------------------------
// FP16 GEMM, 4-stage cp.async pipeline.
// C[M,N] = A[M,K](half) @ BT[N,K](half)^T + bias[N]
// 128x128 block, BK=32, 256 threads (8 warps 2x4), warp tile 64x32.
// Dynamic smem: 4 stages x (A 128x40 + B 128x40) halves = 81920 B.
// ---------------------------------------------------------------------------
#define GSTAGE_H 10240        // halves per stage (A 5120 + B 5120)
#define G_SMEM_BYTES (4 * GSTAGE_H * 2)

template <bool OUT_HALF>
__global__ __launch_bounds__(256)
void gemm_f16_kernel(const __half* __restrict__ A, const __half* __restrict__ BT,
                     const float* __restrict__ bias, void* __restrict__ Cout,
                     int M, int N, int K) {
    extern __shared__ __half sm[];

    const int tid  = threadIdx.x;
    const int lane = tid & 31;
    const int wid  = tid >> 5;
    const int wm   = wid >> 2;
    const int wn   = wid & 3;
    const int g    = lane >> 2;
    const int t    = lane & 3;
    const int bm   = blockIdx.y * 128;
    const int bn   = blockIdx.x * 128;

    float acc[4][4][4];
#pragma unroll
    for (int i = 0; i < 4; i++)
#pragma unroll
        for (int j = 0; j < 4; j++)
#pragma unroll
            for (int r = 0; r < 4; r++) acc[i][j][r] = 0.0f;

    const int a_row = lane & 15;
    const int a_col = (lane >> 4) << 3;
    const int b_row = ((lane >> 4) << 3) + (lane & 7);
    const int b_col = ((lane >> 3) & 1) << 3;

    const int KT = K >> 5;

    auto fill = [&](int j) {
        __half* a_s = sm + (j & 3) * GSTAGE_H;
        __half* b_s = a_s + 5120;
#pragma unroll
        for (int f = tid; f < 1024; f += 256) {
            const int i = f & 511;
            const int r = i >> 2, c = i & 3;
            if (f < 512)
                cp_async16(a_s + r * 40 + c * 8, A + (size_t)(bm + r) * K + j * 32 + c * 8);
            else
                cp_async16(b_s + r * 40 + c * 8, BT + (size_t)(bn + r) * K + j * 32 + c * 8);
        }
        cp_commit();
    };

    fill(0); fill(1); fill(2);

#pragma unroll 1
    for (int kt = 0; kt < KT; kt++) {
        asm volatile("cp.async.wait_group 2;" ::: "memory");
        __syncthreads();

        if (kt + 3 < KT) fill(kt + 3); else cp_commit();

        const __half* a_s = sm + (kt & 3) * GSTAGE_H;
        const __half* b_s = a_s + 5120;
#pragma unroll
        for (int ks8 = 0; ks8 < 2; ks8++) {
            const int ks = ks8 * 16;
            uint32_t af[4][4], bf[4][2];
#pragma unroll
            for (int mt = 0; mt < 4; mt++) {
                const int m0 = wm * 64 + mt * 16;
                ldsm_x4(af[mt][0], af[mt][1], af[mt][2], af[mt][3],
                        smem_u32(a_s + (m0 + a_row) * 40 + ks + a_col));
            }
#pragma unroll
            for (int p = 0; p < 2; p++) {
                const int n0 = wn * 32 + p * 16;
                ldsm_x4(bf[2 * p][0], bf[2 * p][1], bf[2 * p + 1][0], bf[2 * p + 1][1],
                        smem_u32(b_s + (n0 + b_row) * 40 + ks + b_col));
            }
#pragma unroll
            for (int mt = 0; mt < 4; mt++)
#pragma unroll
                for (int nt = 0; nt < 4; nt++)
                    mma_f16(acc[mt][nt][0], acc[mt][nt][1], acc[mt][nt][2], acc[mt][nt][3],
                            af[mt][0], af[mt][1], af[mt][2], af[mt][3],
                            bf[nt][0], bf[nt][1]);
        }
    }

    // Epilogue
#pragma unroll
    for (int mt = 0; mt < 4; mt++) {
        const int row0 = bm + wm * 64 + mt * 16 + g;
#pragma unroll
        for (int nt = 0; nt < 4; nt++) {
            const int col = bn + wn * 32 + nt * 8 + 2 * t;
            const float bx = bias[col], by = bias[col + 1];
            const float v00 = acc[mt][nt][0] + bx, v01 = acc[mt][nt][1] + by;
            const float v10 = acc[mt][nt][2] + bx, v11 = acc[mt][nt][3] + by;
            if (OUT_HALF) {
                __half* C = (__half*)Cout;
                *reinterpret_cast<uint32_t*>(&C[(size_t)row0 * N + col]) = pack_h2(v00, v01);
                *reinterpret_cast<uint32_t*>(&C[(size_t)(row0 + 8) * N + col]) = pack_h2(v10, v11);
            } else {
                float* C = (float*)Cout;
                *reinterpret_cast<float2*>(&C[(size_t)row0 * N + col]) = make_float2(v00, v01);
                *reinterpret_cast<float2*>(&C[(size_t)(row0 + 8) * N + col]) = make_float2(v10, v11);
            }
        }
    }
}

// ---------------------------------------------------------------------------
// FP16 flash attention. grid=(T/128, H, B), 256 threads (8 warps).
// BQ=128 (warp w owns q rows [16w,16w+16)), KV tile 64, double-buffered cp.async.
// ---------------------------------------------------------------------------
#define KSW 72   // 64 + 8 halves (144B row stride, conflict-free ldmatrix)

__global__ __launch_bounds__(256)
void attn_f16_kernel(const __half* __restrict__ qkv, __half* __restrict__ out) {
    __shared__ __half Ks[2][64][KSW];
    __shared__ __half Vs[2][64][KSW];

    const int tid  = threadIdx.x;
    const int lane = tid & 31;
    const int w    = tid >> 5;
    const int g    = lane >> 2;
    const int t    = lane & 3;
    const int qt   = (int)gridDim.x - 1 - (int)blockIdx.x;  // deep tiles first
    const int h    = blockIdx.y;
    const int b    = blockIdx.z;

    const size_t base = (size_t)b * Tseq * C3 + (size_t)h * HD;

    const int a_row = lane & 15;
    const int a_col = (lane >> 4) << 3;
    const int b_row = ((lane >> 4) << 3) + (lane & 7);
    const int b_col = ((lane >> 3) & 1) << 3;

    // ---- Stage Q (128x64) through Ks[0..1], build Q A-frags ----
    for (int f = tid; f < 1024; f += 256) {
        const int r = f >> 3, c = f & 7;
        uint4 v = *reinterpret_cast<const uint4*>(
            &qkv[base + (size_t)(qt * 128 + r) * C3 + c * 8]);
        if (r < 64) *reinterpret_cast<uint4*>(&Ks[0][r][c * 8]) = v;
        else        *reinterpret_cast<uint4*>(&Vs[0][r - 64][c * 8]) = v;
    }
    __syncthreads();

    uint32_t qf[4][4];
    {
        const __half* qsrc = (w < 4) ? &Ks[0][0][0] : &Vs[0][0][0];
        const int qrow = (w * 16) & 63;
#pragma unroll
        for (int kc = 0; kc < 4; kc++)
            ldsm_x4(qf[kc][0], qf[kc][1], qf[kc][2], qf[kc][3],
                    smem_u32(qsrc + (qrow + a_row) * KSW + kc * 16 + a_col));
    }
    __syncthreads();

    float oa[8][4];
#pragma unroll
    for (int i = 0; i < 8; i++)
#pragma unroll
        for (int j = 0; j < 4; j++) oa[i][j] = 0.0f;

    float m0r = -1e30f, m1r = -1e30f, l0 = 0.0f, l1 = 0.0f;
    const int q0g = qt * 128 + w * 16 + g;
    const int q1g = q0g + 8;
    const int nkv = 2 * (qt + 1);

    auto fillKV = [&](int kt) {
        const int buf = kt & 1;
#pragma unroll
        for (int f = tid; f < 512; f += 256) {
            const int r = f >> 3, c = f & 7;
            const size_t off = base + (size_t)(kt * 64 + r) * C3 + c * 8;
            cp_async16(&Ks[buf][r][c * 8], qkv + off + Cdim);
            cp_async16(&Vs[buf][r][c * 8], qkv + off + 2 * Cdim);
        }
        cp_commit();
    };

    fillKV(0);

#pragma unroll 1
    for (int kt = 0; kt < nkv; kt++) {
        if (kt + 1 < nkv) fillKV(kt + 1); else cp_commit();
        asm volatile("cp.async.wait_group 1;" ::: "memory");
        __syncthreads();

        const int buf = kt & 1;

        // ---- S = Q @ K^T ----
        float s[8][4];
#pragma unroll
        for (int i = 0; i < 8; i++)
#pragma unroll
            for (int j = 0; j < 4; j++) s[i][j] = 0.0f;

#pragma unroll
        for (int kc = 0; kc < 4; kc++) {
#pragma unroll
            for (int p = 0; p < 4; p++) {
                uint32_t b0a, b1a, b0b, b1b;
                ldsm_x4(b0a, b1a, b0b, b1b,
                        smem_u32(&Ks[buf][p * 16 + b_row][kc * 16 + b_col]));
                mma_f16(s[2 * p][0], s[2 * p][1], s[2 * p][2], s[2 * p][3],
                        qf[kc][0], qf[kc][1], qf[kc][2], qf[kc][3], b0a, b1a);
                mma_f16(s[2 * p + 1][0], s[2 * p + 1][1], s[2 * p + 1][2], s[2 * p + 1][3],
                        qf[kc][0], qf[kc][1], qf[kc][2], qf[kc][3], b0b, b1b);
            }
        }

#pragma unroll
        for (int nt = 0; nt < 8; nt++)
#pragma unroll
            for (int j = 0; j < 4; j++) s[nt][j] *= 0.125f;

        // causal mask: only last two kv tiles overlap the q range
        if (kt >= nkv - 2) {
#pragma unroll
            for (int nt = 0; nt < 8; nt++) {
                const int k0 = kt * 64 + nt * 8 + 2 * t;
                if (k0 > q0g)     s[nt][0] = -1e30f;
                if (k0 + 1 > q0g) s[nt][1] = -1e30f;
                if (k0 > q1g)     s[nt][2] = -1e30f;
                if (k0 + 1 > q1g) s[nt][3] = -1e30f;
            }
        }

        // ---- streaming softmax ----
        float rmax0 = -1e30f, rmax1 = -1e30f;
#pragma unroll
        for (int nt = 0; nt < 8; nt++) {
            rmax0 = fmaxf(rmax0, fmaxf(s[nt][0], s[nt][1]));
            rmax1 = fmaxf(rmax1, fmaxf(s[nt][2], s[nt][3]));
        }
        rmax0 = fmaxf(rmax0, __shfl_xor_sync(0xffffffffu, rmax0, 1));
        rmax0 = fmaxf(rmax0, __shfl_xor_sync(0xffffffffu, rmax0, 2));
        rmax1 = fmaxf(rmax1, __shfl_xor_sync(0xffffffffu, rmax1, 1));
        rmax1 = fmaxf(rmax1, __shfl_xor_sync(0xffffffffu, rmax1, 2));

        const float mn0 = fmaxf(m0r, rmax0);
        const float mn1 = fmaxf(m1r, rmax1);
        const float al0 = __expf(m0r - mn0);
        const float al1 = __expf(m1r - mn1);
        m0r = mn0; m1r = mn1;

        float rs0 = 0.0f, rs1 = 0.0f;
#pragma unroll
        for (int nt = 0; nt < 8; nt++) {
            s[nt][0] = __expf(s[nt][0] - mn0);
            s[nt][1] = __expf(s[nt][1] - mn0);
            s[nt][2] = __expf(s[nt][2] - mn1);
            s[nt][3] = __expf(s[nt][3] - mn1);
            rs0 += s[nt][0] + s[nt][1];
            rs1 += s[nt][2] + s[nt][3];
        }
        rs0 += __shfl_xor_sync(0xffffffffu, rs0, 1);
        rs0 += __shfl_xor_sync(0xffffffffu, rs0, 2);
        rs1 += __shfl_xor_sync(0xffffffffu, rs1, 1);
        rs1 += __shfl_xor_sync(0xffffffffu, rs1, 2);
        l0 = l0 * al0 + rs0;
        l1 = l1 * al1 + rs1;

#pragma unroll
        for (int dt = 0; dt < 8; dt++) {
            oa[dt][0] *= al0; oa[dt][1] *= al0;
            oa[dt][2] *= al1; oa[dt][3] *= al1;
        }

        // ---- O += P @ V ----
#pragma unroll
        for (int j = 0; j < 4; j++) {
            const uint32_t a0 = pack_h2(s[2 * j][0], s[2 * j][1]);
            const uint32_t a1 = pack_h2(s[2 * j][2], s[2 * j][3]);
            const uint32_t a2 = pack_h2(s[2 * j + 1][0], s[2 * j + 1][1]);
            const uint32_t a3 = pack_h2(s[2 * j + 1][2], s[2 * j + 1][3]);
#pragma unroll
            for (int dp = 0; dp < 4; dp++) {
                uint32_t b0a, b1a, b0b, b1b;
                ldsm_x4_t(b0a, b1a, b0b, b1b,
                          smem_u32(&Vs[buf][j * 16 + a_row][dp * 16 + a_col]));
                mma_f16(oa[2 * dp][0], oa[2 * dp][1], oa[2 * dp][2], oa[2 * dp][3],
                        a0, a1, a2, a3, b0a, b1a);
                mma_f16(oa[2 * dp + 1][0], oa[2 * dp + 1][1], oa[2 * dp + 1][2], oa[2 * dp + 1][3],
                        a0, a1, a2, a3, b0b, b1b);
            }
        }
        __syncthreads();
    }

    // ---- finalize, write half [B,T,C] ----
    const float il0 = 1.0f / l0;
    const float il1 = 1.0f / l1;
    const size_t ob = (size_t)b * Tseq * Cdim + (size_t)h * HD;
    const int r0 = qt * 128 + w * 16 + g;
#pragma unroll
    for (int dt = 0; dt < 8; dt++) {
        const int col = dt * 8 + 2 * t;
        *reinterpret_cast<uint32_t*>(&out[ob + (size_t)r0 * Cdim + col]) =
            pack_h2(oa[dt][0] * il0, oa[dt][1] * il0);
        *reinterpret_cast<uint32_t*>(&out[ob + (size_t)(r0 + 8) * Cdim + col]) =
            pack_h2(oa[dt][2] * il1, oa[dt][3] * il1);
    }
}

// ---------------------------------------------------------------------------
// Launch
// ---------------------------------------------------------------------------
extern "C" void kernel_launch(void* const* d_in, const int* in_sizes, int n_in,
                              void* d_out, int out_size) {
    const float* x      = (const float*)d_in[0];
    const float* w_attn = (const float*)d_in[1];
    const float* b_attn = (const float*)d_in[2];
    const float* w_proj = (const float*)d_in[3];
    const float* b_proj = (const float*)d_in[4];
    float* out = (float*)d_out;

    __half *qkv, *att, *xh, *waT, *wpT;
    cudaGetSymbolAddress((void**)&qkv, g_qkv);
    cudaGetSymbolAddress((void**)&att, g_att);
    cudaGetSymbolAddress((void**)&xh,  g_xh);
    cudaGetSymbolAddress((void**)&waT, g_waT);
    cudaGetSymbolAddress((void**)&wpT, g_wpT);

    cudaFuncSetAttribute(gemm_f16_kernel<true>,
                         cudaFuncAttributeMaxDynamicSharedMemorySize, G_SMEM_BYTES);
    cudaFuncSetAttribute(gemm_f16_kernel<false>,
                         cudaFuncAttributeMaxDynamicSharedMemorySize, G_SMEM_BYTES);

    const int M = Bsz * Tseq;  // 4096

    // Pre-passes
    f32_to_f16_kernel<<<(M * Cdim) / (256 * 4), 256>>>(x, xh);
    {
        dim3 blk(32, 8);
        transpose_f16_kernel<<<dim3(C3 / 32, Cdim / 32), blk>>>(w_attn, waT, Cdim, C3);
        transpose_f16_kernel<<<dim3(Cdim / 32, Cdim / 32), blk>>>(w_proj, wpT, Cdim, Cdim);
    }

    // 1) qkv = x @ w_attn + b_attn   [4096,3072] (half out)
    gemm_f16_kernel<true><<<dim3(C3 / 128, M / 128), 256, G_SMEM_BYTES>>>(
        xh, waT, b_attn, qkv, M, C3, Cdim);

    // 2) attention -> g_att (half)
    attn_f16_kernel<<<dim3(Tseq / 128, Hn, Bsz), 256>>>(qkv, att);

    // 3) out = att @ w_proj + b_proj  [4096,1024] (float out)
    gemm_f16_kernel<false><<<dim3(Cdim / 128, M / 128), 256, G_SMEM_BYTES>>>(
        att, wpT, b_proj, out, M, Cdim, Cdim);
}

// round 6
// speedup vs baseline: 7.3019x; 1.0983x over previous
#include <cuda_runtime.h>
#include <cuda_fp16.h>
#include <cstdint>

// Problem constants
#define Bsz 2
#define Tseq 2048
#define Cdim 1024
#define Hn 16
#define HD 64
#define C3 (3 * Cdim)

// Scratch (allocation-free rule: __device__ globals), fp16 intermediates
__device__ __half g_qkv[Bsz * Tseq * C3];    // [B,T,3C]
__device__ __half g_att[Bsz * Tseq * Cdim];  // [B,T,C]
__device__ __half g_xh[Bsz * Tseq * Cdim];   // x in fp16
__device__ __half g_waT[C3 * Cdim];          // w_attn^T [3C,C]
__device__ __half g_wpT[Cdim * Cdim];        // w_proj^T [C,C]

// ---------------------------------------------------------------------------
// helpers
// ---------------------------------------------------------------------------
__device__ __forceinline__ uint32_t smem_u32(const void* p) {
    return (uint32_t)__cvta_generic_to_shared(p);
}
__device__ __forceinline__ void cp_async16(void* dst, const void* src) {
    asm volatile("cp.async.ca.shared.global [%0], [%1], 16;"
                 :: "r"(smem_u32(dst)), "l"(src));
}
__device__ __forceinline__ void cp_async16_cg(void* dst, const void* src) {
    asm volatile("cp.async.cg.shared.global [%0], [%1], 16;"
                 :: "r"(smem_u32(dst)), "l"(src));
}
__device__ __forceinline__ void cp_commit() { asm volatile("cp.async.commit_group;"); }

__device__ __forceinline__ void ldsm_x4(uint32_t& r0, uint32_t& r1, uint32_t& r2, uint32_t& r3,
                                        uint32_t addr) {
    asm volatile("ldmatrix.sync.aligned.m8n8.x4.shared.b16 {%0,%1,%2,%3}, [%4];"
                 : "=r"(r0), "=r"(r1), "=r"(r2), "=r"(r3) : "r"(addr));
}
__device__ __forceinline__ void ldsm_x4_t(uint32_t& r0, uint32_t& r1, uint32_t& r2, uint32_t& r3,
                                          uint32_t addr) {
    asm volatile("ldmatrix.sync.aligned.m8n8.x4.trans.shared.b16 {%0,%1,%2,%3}, [%4];"
                 : "=r"(r0), "=r"(r1), "=r"(r2), "=r"(r3) : "r"(addr));
}

__device__ __forceinline__ void mma_f16(float& c0, float& c1, float& c2, float& c3,
                                        uint32_t a0, uint32_t a1, uint32_t a2, uint32_t a3,
                                        uint32_t b0, uint32_t b1) {
    asm volatile(
        "mma.sync.aligned.m16n8k16.row.col.f32.f16.f16.f32 "
        "{%0,%1,%2,%3}, {%4,%5,%6,%7}, {%8,%9}, {%0,%1,%2,%3};"
        : "+f"(c0), "+f"(c1), "+f"(c2), "+f"(c3)
        : "r"(a0), "r"(a1), "r"(a2), "r"(a3), "r"(b0), "r"(b1));
}

__device__ __forceinline__ uint32_t pack_h2(float lo, float hi) {
    __half2 h = __floats2half2_rn(lo, hi);
    return *reinterpret_cast<uint32_t*>(&h);
}

// ---------------------------------------------------------------------------
// Pre-passes
// ---------------------------------------------------------------------------
__global__ void f32_to_f16_kernel(const float* __restrict__ in, __half* __restrict__ outp) {
    const int i = (blockIdx.x * blockDim.x + threadIdx.x) * 4;
    float4 v = *reinterpret_cast<const float4*>(in + i);
    *reinterpret_cast<__half2*>(outp + i) = __floats2half2_rn(v.x, v.y);
    *reinterpret_cast<__half2*>(outp + i + 2) = __floats2half2_rn(v.z, v.w);
}

// W [K,N] f32 row-major -> WT [N,K] half row-major
__global__ __launch_bounds__(256)
void transpose_f16_kernel(const float* __restrict__ W, __half* __restrict__ WT,
                          int K, int N) {
    __shared__ float tile[32][33];
    const int bx = blockIdx.x * 32;
    const int by = blockIdx.y * 32;
    const int tx = threadIdx.x, ty = threadIdx.y;
#pragma unroll
    for (int i = 0; i < 32; i += 8)
        tile[ty + i][tx] = W[(size_t)(by + ty + i) * N + bx + tx];
    __syncthreads();
#pragma unroll
    for (int i = 0; i < 32; i += 8)
        WT[(size_t)(bx + ty + i) * K + by + tx] = __float2half_rn(tile[tx][ty + i]);
}

// ---------------------------------------------------------------------------
// FP16 GEMM, 3-stage cp.async pipeline + double-buffered register fragments.
// C[M,N] = A[M,K](half) @ BT[N,K](half)^T + bias[N]
// 128x128 block, BK=32, 256 threads (8 warps 2x4), warp tile 64x32.
// Dynamic smem: 3 stages x (A 128x40 + B 128x40) halves = 61440 B (2 CTA/SM).
// ---------------------------------------------------------------------------
#define GSTAGE_H 10240
#define G_SMEM_BYTES (3 * GSTAGE_H * 2)

template <bool OUT_HALF>
__global__ __launch_bounds__(256, 2)
void gemm_f16_kernel(const __half* __restrict__ A, const __half* __restrict__ BT,
                     const float* __restrict__ bias, void* __restrict__ Cout,
                     int M, int N, int K) {
    extern __shared__ __half sm[];

    const int tid  = threadIdx.x;
    const int lane = tid & 31;
    const int wid  = tid >> 5;
    const int wm   = wid >> 2;
    const int wn   = wid & 3;
    const int g    = lane >> 2;
    const int t    = lane & 3;
    const int bm   = blockIdx.y * 128;
    const int bn   = blockIdx.x * 128;

    float acc[4][4][4];
#pragma unroll
    for (int i = 0; i < 4; i++)
#pragma unroll
        for (int j = 0; j < 4; j++)
#pragma unroll
            for (int r = 0; r < 4; r++) acc[i][j][r] = 0.0f;

    const int a_row = lane & 15;
    const int a_col = (lane >> 4) << 3;
    const int b_row = ((lane >> 4) << 3) + (lane & 7);
    const int b_col = ((lane >> 3) & 1) << 3;

    const int KT = K >> 5;

    auto fill = [&](int j, int st) {
        __half* a_s = sm + st * GSTAGE_H;
        __half* b_s = a_s + 5120;
#pragma unroll
        for (int f = tid; f < 1024; f += 256) {
            const int i = f & 511;
            const int r = i >> 2, c = i & 3;
            if (f < 512)
                cp_async16_cg(a_s + r * 40 + c * 8, A + (size_t)(bm + r) * K + j * 32 + c * 8);
            else
                cp_async16_cg(b_s + r * 40 + c * 8, BT + (size_t)(bn + r) * K + j * 32 + c * 8);
        }
        cp_commit();
    };

    fill(0, 0); fill(1, 1);

    int st_cur = 0;     // stage of kt
    int st_next = 2;    // stage for kt+2
#pragma unroll 1
    for (int kt = 0; kt < KT; kt++) {
        asm volatile("cp.async.wait_group 1;" ::: "memory");
        __syncthreads();

        if (kt + 2 < KT) fill(kt + 2, st_next); else cp_commit();

        const __half* a_s = sm + st_cur * GSTAGE_H;
        const __half* b_s = a_s + 5120;

        // Double-buffered fragments: both k16 sets live -> LDSM(set1) overlaps MMA(set0)
        uint32_t af0[4][4], bf0[4][2], af1[4][4], bf1[4][2];
#pragma unroll
        for (int mt = 0; mt < 4; mt++) {
            const int m0 = wm * 64 + mt * 16;
            ldsm_x4(af0[mt][0], af0[mt][1], af0[mt][2], af0[mt][3],
                    smem_u32(a_s + (m0 + a_row) * 40 + a_col));
        }
#pragma unroll
        for (int p = 0; p < 2; p++) {
            const int n0 = wn * 32 + p * 16;
            ldsm_x4(bf0[2 * p][0], bf0[2 * p][1], bf0[2 * p + 1][0], bf0[2 * p + 1][1],
                    smem_u32(b_s + (n0 + b_row) * 40 + b_col));
        }
#pragma unroll
        for (int mt = 0; mt < 4; mt++) {
            const int m0 = wm * 64 + mt * 16;
            ldsm_x4(af1[mt][0], af1[mt][1], af1[mt][2], af1[mt][3],
                    smem_u32(a_s + (m0 + a_row) * 40 + 16 + a_col));
        }
#pragma unroll
        for (int p = 0; p < 2; p++) {
            const int n0 = wn * 32 + p * 16;
            ldsm_x4(bf1[2 * p][0], bf1[2 * p][1], bf1[2 * p + 1][0], bf1[2 * p + 1][1],
                    smem_u32(b_s + (n0 + b_row) * 40 + 16 + b_col));
        }

#pragma unroll
        for (int mt = 0; mt < 4; mt++)
#pragma unroll
            for (int nt = 0; nt < 4; nt++)
                mma_f16(acc[mt][nt][0], acc[mt][nt][1], acc[mt][nt][2], acc[mt][nt][3],
                        af0[mt][0], af0[mt][1], af0[mt][2], af0[mt][3],
                        bf0[nt][0], bf0[nt][1]);
#pragma unroll
        for (int mt = 0; mt < 4; mt++)
#pragma unroll
            for (int nt = 0; nt < 4; nt++)
                mma_f16(acc[mt][nt][0], acc[mt][nt][1], acc[mt][nt][2], acc[mt][nt][3],
                        af1[mt][0], af1[mt][1], af1[mt][2], af1[mt][3],
                        bf1[nt][0], bf1[nt][1]);

        st_cur = (st_cur == 2) ? 0 : st_cur + 1;
        st_next = (st_next == 2) ? 0 : st_next + 1;
    }

    // Epilogue
#pragma unroll
    for (int mt = 0; mt < 4; mt++) {
        const int row0 = bm + wm * 64 + mt * 16 + g;
#pragma unroll
        for (int nt = 0; nt < 4; nt++) {
            const int col = bn + wn * 32 + nt * 8 + 2 * t;
            const float bx = bias[col], by = bias[col + 1];
            const float v00 = acc[mt][nt][0] + bx, v01 = acc[mt][nt][1] + by;
            const float v10 = acc[mt][nt][2] + bx, v11 = acc[mt][nt][3] + by;
            if (OUT_HALF) {
                __half* C = (__half*)Cout;
                *reinterpret_cast<uint32_t*>(&C[(size_t)row0 * N + col]) = pack_h2(v00, v01);
                *reinterpret_cast<uint32_t*>(&C[(size_t)(row0 + 8) * N + col]) = pack_h2(v10, v11);
            } else {
                float* C = (float*)Cout;
                *reinterpret_cast<float2*>(&C[(size_t)row0 * N + col]) = make_float2(v00, v01);
                *reinterpret_cast<float2*>(&C[(size_t)(row0 + 8) * N + col]) = make_float2(v10, v11);
            }
        }
    }
}

// ---------------------------------------------------------------------------
// FP16 flash attention. grid=(T/128, H, B), 256 threads (8 warps).
// BQ=128, KV tile 64, double-buffered cp.async. exp2-domain softmax.
// ---------------------------------------------------------------------------
#define KSW 72   // 64 + 8 halves (conflict-free ldmatrix)
#define SCL 0.18033688f   // 0.125 * log2(e)

__global__ __launch_bounds__(256)
void attn_f16_kernel(const __half* __restrict__ qkv, __half* __restrict__ out) {
    __shared__ __half Ks[2][64][KSW];
    __shared__ __half Vs[2][64][KSW];

    const int tid  = threadIdx.x;
    const int lane = tid & 31;
    const int w    = tid >> 5;
    const int g    = lane >> 2;
    const int t    = lane & 3;
    const int qt   = (int)gridDim.x - 1 - (int)blockIdx.x;  // deep tiles first
    const int h    = blockIdx.y;
    const int b    = blockIdx.z;

    const size_t base = (size_t)b * Tseq * C3 + (size_t)h * HD;

    const int a_row = lane & 15;
    const int a_col = (lane >> 4) << 3;
    const int b_row = ((lane >> 4) << 3) + (lane & 7);
    const int b_col = ((lane >> 3) & 1) << 3;

    // ---- Stage Q (128x64) through Ks/Vs buffers, build Q A-frags ----
    for (int f = tid; f < 1024; f += 256) {
        const int r = f >> 3, c = f & 7;
        uint4 v = *reinterpret_cast<const uint4*>(
            &qkv[base + (size_t)(qt * 128 + r) * C3 + c * 8]);
        if (r < 64) *reinterpret_cast<uint4*>(&Ks[0][r][c * 8]) = v;
        else        *reinterpret_cast<uint4*>(&Vs[0][r - 64][c * 8]) = v;
    }
    __syncthreads();

    uint32_t qf[4][4];
    {
        const __half* qsrc = (w < 4) ? &Ks[0][0][0] : &Vs[0][0][0];
        const int qrow = (w * 16) & 63;
#pragma unroll
        for (int kc = 0; kc < 4; kc++)
            ldsm_x4(qf[kc][0], qf[kc][1], qf[kc][2], qf[kc][3],
                    smem_u32(qsrc + (qrow + a_row) * KSW + kc * 16 + a_col));
    }
    __syncthreads();

    float oa[8][4];
#pragma unroll
    for (int i = 0; i < 8; i++)
#pragma unroll
        for (int j = 0; j < 4; j++) oa[i][j] = 0.0f;

    float m0r = -1e30f, m1r = -1e30f, l0 = 0.0f, l1 = 0.0f;
    const int q0g = qt * 128 + w * 16 + g;
    const int q1g = q0g + 8;
    const int nkv = 2 * (qt + 1);

    auto fillKV = [&](int kt) {
        const int buf = kt & 1;
#pragma unroll
        for (int f = tid; f < 512; f += 256) {
            const int r = f >> 3, c = f & 7;
            const size_t off = base + (size_t)(kt * 64 + r) * C3 + c * 8;
            cp_async16(&Ks[buf][r][c * 8], qkv + off + Cdim);
            cp_async16(&Vs[buf][r][c * 8], qkv + off + 2 * Cdim);
        }
        cp_commit();
    };

    fillKV(0);

#pragma unroll 1
    for (int kt = 0; kt < nkv; kt++) {
        if (kt + 1 < nkv) fillKV(kt + 1); else cp_commit();
        asm volatile("cp.async.wait_group 1;" ::: "memory");
        __syncthreads();

        const int buf = kt & 1;

        // ---- S = Q @ K^T (then into log2 domain via single scale) ----
        float s[8][4];
#pragma unroll
        for (int i = 0; i < 8; i++)
#pragma unroll
            for (int j = 0; j < 4; j++) s[i][j] = 0.0f;

#pragma unroll
        for (int kc = 0; kc < 4; kc++) {
#pragma unroll
            for (int p = 0; p < 4; p++) {
                uint32_t b0a, b1a, b0b, b1b;
                ldsm_x4(b0a, b1a, b0b, b1b,
                        smem_u32(&Ks[buf][p * 16 + b_row][kc * 16 + b_col]));
                mma_f16(s[2 * p][0], s[2 * p][1], s[2 * p][2], s[2 * p][3],
                        qf[kc][0], qf[kc][1], qf[kc][2], qf[kc][3], b0a, b1a);
                mma_f16(s[2 * p + 1][0], s[2 * p + 1][1], s[2 * p + 1][2], s[2 * p + 1][3],
                        qf[kc][0], qf[kc][1], qf[kc][2], qf[kc][3], b0b, b1b);
            }
        }

#pragma unroll
        for (int nt = 0; nt < 8; nt++)
#pragma unroll
            for (int j = 0; j < 4; j++) s[nt][j] *= SCL;

        // causal mask: only last two kv tiles overlap the q range
        if (kt >= nkv - 2) {
#pragma unroll
            for (int nt = 0; nt < 8; nt++) {
                const int k0 = kt * 64 + nt * 8 + 2 * t;
                if (k0 > q0g)     s[nt][0] = -1e30f;
                if (k0 + 1 > q0g) s[nt][1] = -1e30f;
                if (k0 > q1g)     s[nt][2] = -1e30f;
                if (k0 + 1 > q1g) s[nt][3] = -1e30f;
            }
        }

        // ---- streaming softmax in exp2 domain ----
        float rmax0 = -1e30f, rmax1 = -1e30f;
#pragma unroll
        for (int nt = 0; nt < 8; nt++) {
            rmax0 = fmaxf(rmax0, fmaxf(s[nt][0], s[nt][1]));
            rmax1 = fmaxf(rmax1, fmaxf(s[nt][2], s[nt][3]));
        }
        rmax0 = fmaxf(rmax0, __shfl_xor_sync(0xffffffffu, rmax0, 1));
        rmax0 = fmaxf(rmax0, __shfl_xor_sync(0xffffffffu, rmax0, 2));
        rmax1 = fmaxf(rmax1, __shfl_xor_sync(0xffffffffu, rmax1, 1));
        rmax1 = fmaxf(rmax1, __shfl_xor_sync(0xffffffffu, rmax1, 2));

        const float mn0 = fmaxf(m0r, rmax0);
        const float mn1 = fmaxf(m1r, rmax1);
        const float al0 = exp2f(m0r - mn0);
        const float al1 = exp2f(m1r - mn1);
        m0r = mn0; m1r = mn1;

        float rs0 = 0.0f, rs1 = 0.0f;
#pragma unroll
        for (int nt = 0; nt < 8; nt++) {
            s[nt][0] = exp2f(s[nt][0] - mn0);
            s[nt][1] = exp2f(s[nt][1] - mn0);
            s[nt][2] = exp2f(s[nt][2] - mn1);
            s[nt][3] = exp2f(s[nt][3] - mn1);
            rs0 += s[nt][0] + s[nt][1];
            rs1 += s[nt][2] + s[nt][3];
        }
        rs0 += __shfl_xor_sync(0xffffffffu, rs0, 1);
        rs0 += __shfl_xor_sync(0xffffffffu, rs0, 2);
        rs1 += __shfl_xor_sync(0xffffffffu, rs1, 1);
        rs1 += __shfl_xor_sync(0xffffffffu, rs1, 2);
        l0 = l0 * al0 + rs0;
        l1 = l1 * al1 + rs1;

#pragma unroll
        for (int dt = 0; dt < 8; dt++) {
            oa[dt][0] *= al0; oa[dt][1] *= al0;
            oa[dt][2] *= al1; oa[dt][3] *= al1;
        }

        // ---- O += P @ V ----
#pragma unroll
        for (int j = 0; j < 4; j++) {
            const uint32_t a0 = pack_h2(s[2 * j][0], s[2 * j][1]);
            const uint32_t a1 = pack_h2(s[2 * j][2], s[2 * j][3]);
            const uint32_t a2 = pack_h2(s[2 * j + 1][0], s[2 * j + 1][1]);
            const uint32_t a3 = pack_h2(s[2 * j + 1][2], s[2 * j + 1][3]);
#pragma unroll
            for (int dp = 0; dp < 4; dp++) {
                uint32_t b0a, b1a, b0b, b1b;
                ldsm_x4_t(b0a, b1a, b0b, b1b,
                          smem_u32(&Vs[buf][j * 16 + a_row][dp * 16 + a_col]));
                mma_f16(oa[2 * dp][0], oa[2 * dp][1], oa[2 * dp][2], oa[2 * dp][3],
                        a0, a1, a2, a3, b0a, b1a);
                mma_f16(oa[2 * dp + 1][0], oa[2 * dp + 1][1], oa[2 * dp + 1][2], oa[2 * dp + 1][3],
                        a0, a1, a2, a3, b0b, b1b);
            }
        }
        __syncthreads();
    }

    // ---- finalize, write half [B,T,C] ----
    const float il0 = 1.0f / l0;
    const float il1 = 1.0f / l1;
    const size_t ob = (size_t)b * Tseq * Cdim + (size_t)h * HD;
    const int r0 = qt * 128 + w * 16 + g;
#pragma unroll
    for (int dt = 0; dt < 8; dt++) {
        const int col = dt * 8 + 2 * t;
        *reinterpret_cast<uint32_t*>(&out[ob + (size_t)r0 * Cdim + col]) =
            pack_h2(oa[dt][0] * il0, oa[dt][1] * il0);
        *reinterpret_cast<uint32_t*>(&out[ob + (size_t)(r0 + 8) * Cdim + col]) =
            pack_h2(oa[dt][2] * il1, oa[dt][3] * il1);
    }
}

// ---------------------------------------------------------------------------
// Launch
// ---------------------------------------------------------------------------
extern "C" void kernel_launch(void* const* d_in, const int* in_sizes, int n_in,
                              void* d_out, int out_size) {
    const float* x      = (const float*)d_in[0];
    const float* w_attn = (const float*)d_in[1];
    const float* b_attn = (const float*)d_in[2];
    const float* w_proj = (const float*)d_in[3];
    const float* b_proj = (const float*)d_in[4];
    float* out = (float*)d_out;

    __half *qkv, *att, *xh, *waT, *wpT;
    cudaGetSymbolAddress((void**)&qkv, g_qkv);
    cudaGetSymbolAddress((void**)&att, g_att);
    cudaGetSymbolAddress((void**)&xh,  g_xh);
    cudaGetSymbolAddress((void**)&waT, g_waT);
    cudaGetSymbolAddress((void**)&wpT, g_wpT);

    cudaFuncSetAttribute(gemm_f16_kernel<true>,
                         cudaFuncAttributeMaxDynamicSharedMemorySize, G_SMEM_BYTES);
    cudaFuncSetAttribute(gemm_f16_kernel<false>,
                         cudaFuncAttributeMaxDynamicSharedMemorySize, G_SMEM_BYTES);

    const int M = Bsz * Tseq;  // 4096

    // Pre-passes
    f32_to_f16_kernel<<<(M * Cdim) / (256 * 4), 256>>>(x, xh);
    {
        dim3 blk(32, 8);
        transpose_f16_kernel<<<dim3(C3 / 32, Cdim / 32), blk>>>(w_attn, waT, Cdim, C3);
        transpose_f16_kernel<<<dim3(Cdim / 32, Cdim / 32), blk>>>(w_proj, wpT, Cdim, Cdim);
    }

    // 1) qkv = x @ w_attn + b_attn   [4096,3072] (half out)
    gemm_f16_kernel<true><<<dim3(C3 / 128, M / 128), 256, G_SMEM_BYTES>>>(
        xh, waT, b_attn, qkv, M, C3, Cdim);

    // 2) attention -> g_att (half)
    attn_f16_kernel<<<dim3(Tseq / 128, Hn, Bsz), 256>>>(qkv, att);

    // 3) out = att @ w_proj + b_proj  [4096,1024] (float out)
    gemm_f16_kernel<false><<<dim3(Cdim / 128, M / 128), 256, G_SMEM_BYTES>>>(
        att, wpT, b_proj, out, M, Cdim, Cdim);
}